// round 1
// baseline (speedup 1.0000x reference)
#include <cuda_runtime.h>
#include <math.h>

#define NN 100000
#define EE 1600000
#define HH 128
#define LL 5

// ---------------- device scratch (static; no allocations allowed) ----------
__device__ float g_zcur[NN * HH];     // current activation
__device__ float g_x0[NN * HH];       // initial residual
__device__ float g_h[NN * HH];        // propagated+blended features
__device__ float g_zs[4 * NN * HH];   // per-layer conv outputs for JK
__device__ float g_Wp[LL * HH * HH];  // (1-beta)I + beta*W per layer
__device__ int   g_deg[NN];
__device__ int   g_rowptr[NN + 1];
__device__ int   g_cursor[NN];
__device__ int   g_col[EE];
__device__ int   g_is64;
__device__ float g_bnsum[HH];
__device__ float g_bnsq[HH];

// ---------------- helpers --------------------------------------------------
__device__ __forceinline__ int edge_at(const void* buf, int e) {
    if (g_is64) return (int)((const long long*)buf)[e];
    return ((const int*)buf)[e];
}

// Detect whether edge buffers are int64 (high words all zero) or int32.
__global__ void detect64_k(const void* srcbuf) {
    const unsigned int* p = (const unsigned int*)srcbuf;
    int any = 0;
    for (int i = 1; i < 512; i += 2) any |= (p[i] != 0u);
    g_is64 = any ? 0 : 1;
}

__global__ void zero_csr_k() {
    int i = blockIdx.x * blockDim.x + threadIdx.x;
    if (i < NN) { g_deg[i] = 0; g_cursor[i] = 0; }
}

__global__ void hist_k(const void* dstbuf) {
    for (int e = blockIdx.x * blockDim.x + threadIdx.x; e < EE;
         e += gridDim.x * blockDim.x) {
        atomicAdd(&g_deg[edge_at(dstbuf, e)], 1);
    }
}

// Single-block exclusive scan over g_deg -> g_rowptr (N=100000, chunked).
__global__ void scan_k() {
    __shared__ int warp_tot[32];
    __shared__ int s_carry;
    int tid = threadIdx.x;           // 1024 threads
    int lane = tid & 31, wid = tid >> 5;
    if (tid == 0) s_carry = 0;
    __syncthreads();
    for (int base = 0; base < NN; base += 1024) {
        int i = base + tid;
        int v = (i < NN) ? g_deg[i] : 0;
        int x = v;
        #pragma unroll
        for (int d = 1; d < 32; d <<= 1) {
            int y = __shfl_up_sync(0xFFFFFFFFu, x, d);
            if (lane >= d) x += y;
        }
        if (lane == 31) warp_tot[wid] = x;
        __syncthreads();
        if (wid == 0) {
            int t = warp_tot[lane];
            int tx = t;
            #pragma unroll
            for (int d = 1; d < 32; d <<= 1) {
                int y = __shfl_up_sync(0xFFFFFFFFu, tx, d);
                if (lane >= d) tx += y;
            }
            warp_tot[lane] = tx - t;  // exclusive warp offsets
        }
        __syncthreads();
        int incl = x + warp_tot[wid] + s_carry;
        if (i < NN) g_rowptr[i] = incl - v;
        __syncthreads();
        if (tid == 1023) s_carry = incl;
        __syncthreads();
    }
    if (tid == 0) g_rowptr[NN] = s_carry;
}

__global__ void fill_k(const void* srcbuf, const void* dstbuf) {
    for (int e = blockIdx.x * blockDim.x + threadIdx.x; e < EE;
         e += gridDim.x * blockDim.x) {
        int d = edge_at(dstbuf, e);
        int s = edge_at(srcbuf, e);
        int pos = atomicAdd(&g_cursor[d], 1);
        g_col[g_rowptr[d] + pos] = s;
    }
}

// Wp[l] = beta_l * convW[l] + (1-beta_l) * I
__global__ void prep_w_k(const float* __restrict__ convW,
                         float b0, float b1, float b2, float b3, float b4) {
    int i = blockIdx.x * blockDim.x + threadIdx.x;
    if (i >= LL * HH * HH) return;
    int l = i / (HH * HH);
    int r = (i / HH) % HH;
    int c = i % HH;
    float bl = (l == 0) ? b0 : (l == 1) ? b1 : (l == 2) ? b2 : (l == 3) ? b3 : b4;
    float v = bl * convW[i];
    if (r == c) v += (1.0f - bl);
    g_Wp[i] = v;
}

// ---------------- gather: h = 0.9 * (A @ z) + 0.1 * x0 ---------------------
__global__ void gather_k(const float* __restrict__ z,
                         const float* __restrict__ x0,
                         float* __restrict__ h) {
    int gw = (blockIdx.x * blockDim.x + threadIdx.x) >> 5;
    if (gw >= NN) return;
    int lane = threadIdx.x & 31;
    int beg = g_rowptr[gw], end = g_rowptr[gw + 1];
    float4 acc = make_float4(0.f, 0.f, 0.f, 0.f);
    int e = beg;
    for (; e + 3 < end; e += 4) {
        int s0 = g_col[e], s1 = g_col[e + 1], s2 = g_col[e + 2], s3 = g_col[e + 3];
        float4 v0 = ((const float4*)(z + (long)s0 * HH))[lane];
        float4 v1 = ((const float4*)(z + (long)s1 * HH))[lane];
        float4 v2 = ((const float4*)(z + (long)s2 * HH))[lane];
        float4 v3 = ((const float4*)(z + (long)s3 * HH))[lane];
        acc.x += (v0.x + v1.x) + (v2.x + v3.x);
        acc.y += (v0.y + v1.y) + (v2.y + v3.y);
        acc.z += (v0.z + v1.z) + (v2.z + v3.z);
        acc.w += (v0.w + v1.w) + (v2.w + v3.w);
    }
    for (; e < end; ++e) {
        int s = g_col[e];
        float4 v = ((const float4*)(z + (long)s * HH))[lane];
        acc.x += v.x; acc.y += v.y; acc.z += v.z; acc.w += v.w;
    }
    float4 xv = ((const float4*)(x0 + (long)gw * HH))[lane];
    float4 o;
    const float A1 = 1.0f - 0.1f, A0 = 0.1f;
    o.x = A1 * acc.x + A0 * xv.x;
    o.y = A1 * acc.y + A0 * xv.y;
    o.z = A1 * acc.z + A0 * xv.z;
    o.w = A1 * acc.w + A0 * xv.w;
    ((float4*)(h + (long)gw * HH))[lane] = o;
}

// ---------------- SGEMM: C[N x 128] = A[N x K] @ B[K x 128] (+bias) --------
// MODE 0: C = A@B + bias, and also write a copy to C2 (input layer -> z, x0)
// MODE 1: C = A@B (conv layer with precombined Wp)
// MODE 2: JK: A is the virtual concat of A0..A3 (each N x 128), K = 512, +bias
#define BM 128
#define BK 16

template <int MODE>
__global__ __launch_bounds__(256) void gemm_k(
    const float* __restrict__ A0, const float* __restrict__ A1,
    const float* __restrict__ A2, const float* __restrict__ A3,
    const float* __restrict__ B, const float* __restrict__ bias,
    float* __restrict__ C, float* __restrict__ C2, int K) {
    __shared__ float As[BK][BM + 4];
    __shared__ float Bs[BK][HH];

    int block_row = blockIdx.x * BM;
    int tid = threadIdx.x;
    int tx = tid & 15;      // 16 cols of threads
    int ty = tid >> 4;      // 16 rows of threads

    float acc[8][8];
    #pragma unroll
    for (int i = 0; i < 8; i++)
        #pragma unroll
        for (int j = 0; j < 8; j++) acc[i][j] = 0.f;

    for (int k0 = 0; k0 < K; k0 += BK) {
        const float* Ab;
        int kloc;
        if (MODE == 2) {
            int seg = k0 >> 7;
            Ab = (seg == 0) ? A0 : (seg == 1) ? A1 : (seg == 2) ? A2 : A3;
            kloc = k0 & 127;
        } else {
            Ab = A0;
            kloc = k0;
        }
        // load A tile (BM x BK), transposed into As
        #pragma unroll
        for (int s = tid; s < (BM * BK) / 4; s += 256) {
            int row = s >> 2;
            int kv = (s & 3) * 4;
            float4 v = make_float4(0.f, 0.f, 0.f, 0.f);
            int grow = block_row + row;
            if (grow < NN) v = *(const float4*)(Ab + (long)grow * HH + kloc + kv);
            As[kv + 0][row] = v.x;
            As[kv + 1][row] = v.y;
            As[kv + 2][row] = v.z;
            As[kv + 3][row] = v.w;
        }
        // load B tile (BK x 128)
        #pragma unroll
        for (int s = tid; s < (BK * HH) / 4; s += 256) {
            int kk = s >> 5;
            int c4 = (s & 31) * 4;
            *(float4*)&Bs[kk][c4] = *(const float4*)(B + (long)(k0 + kk) * HH + c4);
        }
        __syncthreads();
        #pragma unroll
        for (int kk = 0; kk < BK; ++kk) {
            float a[8], b[8];
            #pragma unroll
            for (int j = 0; j < 4; j++) {
                a[j]     = As[kk][ty * 4 + j];
                a[4 + j] = As[kk][64 + ty * 4 + j];
                b[j]     = Bs[kk][tx * 4 + j];
                b[4 + j] = Bs[kk][64 + tx * 4 + j];
            }
            #pragma unroll
            for (int im = 0; im < 8; im++)
                #pragma unroll
                for (int in_ = 0; in_ < 8; in_++)
                    acc[im][in_] += a[im] * b[in_];
        }
        __syncthreads();
    }
    // epilogue
    #pragma unroll
    for (int im = 0; im < 8; im++) {
        int row = (im < 4) ? (ty * 4 + im) : (64 + ty * 4 + im - 4);
        int grow = block_row + row;
        if (grow >= NN) continue;
        #pragma unroll
        for (int half = 0; half < 2; half++) {
            int c = half * 64 + tx * 4;
            float4 v;
            v.x = acc[im][half * 4 + 0];
            v.y = acc[im][half * 4 + 1];
            v.z = acc[im][half * 4 + 2];
            v.w = acc[im][half * 4 + 3];
            if (MODE != 1) {
                v.x += bias[c + 0]; v.y += bias[c + 1];
                v.z += bias[c + 2]; v.w += bias[c + 3];
            }
            *(float4*)(C + (long)grow * HH + c) = v;
            if (MODE == 0) *(float4*)(C2 + (long)grow * HH + c) = v;
        }
    }
}

// ---------------- BatchNorm ------------------------------------------------
__global__ void zero_bn_k() {
    int c = threadIdx.x;
    g_bnsum[c] = 0.f;
    g_bnsq[c] = 0.f;
}

__global__ void bn_stats_k(const float* __restrict__ z) {
    int c = threadIdx.x;  // 128 threads
    float s = 0.f, q = 0.f;
    for (int r = blockIdx.x; r < NN; r += gridDim.x) {
        float v = z[(long)r * HH + c];
        s += v;
        q += v * v;
    }
    atomicAdd(&g_bnsum[c], s);
    atomicAdd(&g_bnsq[c], q);
}

__global__ void bn_apply_k(const float* __restrict__ zin,
                           const float* __restrict__ gamma,
                           const float* __restrict__ beta,
                           float* __restrict__ zout) {
    int i = blockIdx.x * blockDim.x + threadIdx.x;
    if (i >= NN * HH) return;
    int c = i & (HH - 1);
    float invN = 1.0f / (float)NN;
    float m = g_bnsum[c] * invN;
    float var = g_bnsq[c] * invN - m * m;
    float r = rsqrtf(var + 1e-5f);
    float v = (zin[i] - m) * r * gamma[c] + beta[c];
    zout[i] = v > 0.f ? v : 0.f;
}

// ---------------- host orchestration ---------------------------------------
extern "C" void kernel_launch(void* const* d_in, const int* in_sizes, int n_in,
                              void* d_out, int out_size) {
    const float* x     = (const float*)d_in[0];
    const float* W_in  = (const float*)d_in[1];
    const float* b_in  = (const float*)d_in[2];
    const float* convW = (const float*)d_in[3];
    const float* gma   = (const float*)d_in[4];
    const float* bta   = (const float*)d_in[5];
    const float* W_jk  = (const float*)d_in[6];
    const float* b_jk  = (const float*)d_in[7];
    const void*  src   = d_in[8];
    const void*  dst   = d_in[9];
    float* out = (float*)d_out;

    void *pz, *px0, *ph, *pzs, *pwp;
    cudaGetSymbolAddress(&pz, g_zcur);
    cudaGetSymbolAddress(&px0, g_x0);
    cudaGetSymbolAddress(&ph, g_h);
    cudaGetSymbolAddress(&pzs, g_zs);
    cudaGetSymbolAddress(&pwp, g_Wp);
    float* zcur = (float*)pz;
    float* x0   = (float*)px0;
    float* h    = (float*)ph;
    float* zs0  = (float*)pzs;
    float* zs1  = zs0 + (long)NN * HH;
    float* zs2  = zs1 + (long)NN * HH;
    float* zs3  = zs2 + (long)NN * HH;
    float* Wp   = (float*)pwp;

    float bl[LL];
    for (int i = 0; i < LL; i++) bl[i] = (float)log(0.5 / (double)(i + 1) + 1.0);

    const int GEMM_BLOCKS = (NN + BM - 1) / BM;          // 782
    const int GATHER_BLOCKS = (NN * 32 + 255) / 256;     // 12500
    const int EW_BLOCKS = (NN * HH + 255) / 256;         // 50000

    // CSR build
    zero_csr_k<<<(NN + 255) / 256, 256>>>();
    detect64_k<<<1, 1>>>(src);
    hist_k<<<1024, 256>>>(dst);
    scan_k<<<1, 1024>>>();
    fill_k<<<1024, 256>>>(src, dst);
    prep_w_k<<<(LL * HH * HH + 255) / 256, 256>>>(convW, bl[0], bl[1], bl[2], bl[3], bl[4]);

    // input layer: z = x @ W_in + b_in; x0 = z
    gemm_k<0><<<GEMM_BLOCKS, 256>>>(x, 0, 0, 0, W_in, b_in, zcur, x0, HH);

    float* zsbuf[4] = {zs0, zs1, zs2, zs3};
    for (int i = 0; i < LL; i++) {
        gather_k<<<GATHER_BLOCKS, 256>>>(zcur, x0, h);
        float* Cout = (i < 4) ? zsbuf[i] : out;
        gemm_k<1><<<GEMM_BLOCKS, 256>>>(h, 0, 0, 0, Wp + (long)i * HH * HH, 0, Cout, 0, HH);
        if (i < 3) {
            zero_bn_k<<<1, HH>>>();
            bn_stats_k<<<512, HH>>>(zsbuf[i]);
            bn_apply_k<<<EW_BLOCKS, 256>>>(zsbuf[i], gma + i * HH, bta + i * HH, zcur);
        } else if (i == 3) {
            gemm_k<2><<<GEMM_BLOCKS, 256>>>(zs0, zs1, zs2, zs3, W_jk, b_jk, zcur, 0, 4 * HH);
        }
    }
    (void)in_sizes; (void)n_in; (void)out_size;
}

// round 4
// speedup vs baseline: 1.1910x; 1.1910x over previous
#include <cuda_runtime.h>
#include <cuda_bf16.h>
#include <math.h>
#include <stdint.h>

#define NN 100000
#define EE 1600000
#define HH 128
#define LL 5

// ---------------- device scratch (static; no allocations allowed) ----------
__device__ float g_zcur[NN * HH];     // current activation
__device__ float g_x0[NN * HH];       // initial residual
__device__ float g_h[NN * HH];        // propagated+blended features
__device__ float g_zs[4 * NN * HH];   // per-layer conv outputs for JK
__device__ int   g_deg[NN];
__device__ int   g_rowptr[NN + 1];
__device__ int   g_cursor[NN];
__device__ int   g_col[EE];
__device__ int   g_is64;
__device__ int   g_part[128];
__device__ int   g_partoff[128];
__device__ float g_bnsum[HH];
__device__ float g_bnsq[HH];

// ---------------- helpers ---------------------------------------------------
__device__ __forceinline__ uint32_t smem_u32(const void* p) {
    uint32_t a;
    asm("{ .reg .u64 t; cvta.to.shared.u64 t, %1; cvt.u32.u64 %0, t; }"
        : "=r"(a) : "l"(p));
    return a;
}

static __device__ __forceinline__ uint32_t pack_bf2(float a, float b) {
    __nv_bfloat162 t = __floats2bfloat162_rn(a, b);
    return *(uint32_t*)&t;
}

// XOR-swizzled byte offset inside a 128x128 bf16 tile (pitch 256B).
// chunk(16B) index XORed with (row & 7): conflict-free ldmatrix + fills.
__device__ __forceinline__ int swz(int row, int col) {
    return row * 256 + ((((col >> 3) ^ (row & 7)) & 15) << 4) + ((col & 7) << 1);
}

#define LDMX4(r0, r1, r2, r3, addr) \
    asm volatile("ldmatrix.sync.aligned.m8n8.x4.shared.b16 {%0,%1,%2,%3}, [%4];" \
                 : "=r"(r0), "=r"(r1), "=r"(r2), "=r"(r3) : "r"(addr))

#define MMA16816(c, a, b0, b1) \
    asm volatile( \
        "mma.sync.aligned.m16n8k16.row.col.f32.bf16.bf16.f32 " \
        "{%0,%1,%2,%3}, {%4,%5,%6,%7}, {%8,%9}, {%0,%1,%2,%3};" \
        : "+f"((c)[0]), "+f"((c)[1]), "+f"((c)[2]), "+f"((c)[3]) \
        : "r"((a)[0]), "r"((a)[1]), "r"((a)[2]), "r"((a)[3]), "r"(b0), "r"(b1))

// SMEM layout (dynamic): 4 bf16 tiles of 32 KB
#define SM_AH 0
#define SM_AL 32768
#define SM_BH 65536
#define SM_BL 98304
#define SM_TOTAL 131072

// ---------------- tensor-core GEMM (mma.sync bf16 split) --------------------
// C[N x 128] = concat(A0..A{nch-1})[N x nch*128] @ Bmma + (bias)
// Bmma[k][n] = wscale * W[k*H + n] + (k==n ? ident : 0)   (single-chunk modes)
// MODE 0: +bias, copy to C2.  MODE 1: plain.  MODE 2: 4 chunks (K=512), +bias.
template <int MODE>
__global__ __launch_bounds__(256, 1) void gemm_tc_k(
    const float* __restrict__ A0, const float* __restrict__ A1,
    const float* __restrict__ A2, const float* __restrict__ A3,
    const float* __restrict__ W, const float* __restrict__ bias,
    float wscale, float ident,
    float* __restrict__ C, float* __restrict__ C2) {
    extern __shared__ char smem[];
    uint32_t sb = smem_u32(smem);
    const int tid = threadIdx.x;
    const int wid = tid >> 5, lane = tid & 31;
    const int block_row = blockIdx.x * 128;

    const int wm = (wid & 3) * 32;   // warp row base in tile
    const int wn = (wid >> 2) * 64;  // warp col base in tile
    const int lrow = lane & 7, quad = lane >> 3;

    float acc[2][8][4];
    #pragma unroll
    for (int i = 0; i < 2; i++)
        #pragma unroll
        for (int j = 0; j < 8; j++)
            #pragma unroll
            for (int q = 0; q < 4; q++) acc[i][j][q] = 0.f;

    const int NCH = (MODE == 2) ? 4 : 1;
    for (int c = 0; c < NCH; c++) {
        const float* Ab = (c == 0) ? A0 : (c == 1) ? A1 : (c == 2) ? A2 : A3;
        // ---- A tile fill: fp32 -> (hi, lo) bf16, swizzled ----
        {
            int row = tid >> 1;
            int cb = (tid & 1) << 6;
            int grow = block_row + row;
            const float4* srcp = (const float4*)(Ab + (long)grow * HH + cb);
            #pragma unroll
            for (int jj = 0; jj < 8; jj++) {
                float4 v0 = make_float4(0.f, 0.f, 0.f, 0.f), v1 = v0;
                if (grow < NN) { v0 = srcp[jj * 2]; v1 = srcp[jj * 2 + 1]; }
                __nv_bfloat16 h0 = __float2bfloat16_rn(v0.x);
                __nv_bfloat16 h1 = __float2bfloat16_rn(v0.y);
                __nv_bfloat16 h2 = __float2bfloat16_rn(v0.z);
                __nv_bfloat16 h3 = __float2bfloat16_rn(v0.w);
                __nv_bfloat16 h4 = __float2bfloat16_rn(v1.x);
                __nv_bfloat16 h5 = __float2bfloat16_rn(v1.y);
                __nv_bfloat16 h6 = __float2bfloat16_rn(v1.z);
                __nv_bfloat16 h7 = __float2bfloat16_rn(v1.w);
                uint4 hv, lv;
                hv.x = pack_bf2(__bfloat162float(h0), __bfloat162float(h1));
                hv.y = pack_bf2(__bfloat162float(h2), __bfloat162float(h3));
                hv.z = pack_bf2(__bfloat162float(h4), __bfloat162float(h5));
                hv.w = pack_bf2(__bfloat162float(h6), __bfloat162float(h7));
                lv.x = pack_bf2(v0.x - __bfloat162float(h0), v0.y - __bfloat162float(h1));
                lv.y = pack_bf2(v0.z - __bfloat162float(h2), v0.w - __bfloat162float(h3));
                lv.z = pack_bf2(v1.x - __bfloat162float(h4), v1.y - __bfloat162float(h5));
                lv.w = pack_bf2(v1.z - __bfloat162float(h6), v1.w - __bfloat162float(h7));
                int so = swz(row, cb + jj * 8);
                *(uint4*)(smem + SM_AH + so) = hv;
                *(uint4*)(smem + SM_AL + so) = lv;
            }
        }
        // ---- B tile fill: smem[n][k] = wscale*W[(c*128+k)*H+n] (+ident diag),
        //      [n][k] row-major == col-major B for mma .col ----
        {
            int n = tid >> 1;
            int kb = (tid & 1) << 6;
            const float* Wb = W + (long)(c * HH + kb) * HH + n;
            #pragma unroll
            for (int jj = 0; jj < 8; jj++) {
                int k0 = kb + jj * 8;
                float vv[8];
                #pragma unroll
                for (int t = 0; t < 8; t++) {
                    float w = Wb[(long)(jj * 8 + t) * HH];
                    vv[t] = wscale * w + ((k0 + t) == n ? ident : 0.f);
                }
                uint4 hv, lv;
                uint32_t* hp = &hv.x;
                uint32_t* lp = &lv.x;
                #pragma unroll
                for (int t = 0; t < 4; t++) {
                    __nv_bfloat16 ha = __float2bfloat16_rn(vv[t * 2]);
                    __nv_bfloat16 hb = __float2bfloat16_rn(vv[t * 2 + 1]);
                    hp[t] = pack_bf2(__bfloat162float(ha), __bfloat162float(hb));
                    lp[t] = pack_bf2(vv[t * 2] - __bfloat162float(ha),
                                     vv[t * 2 + 1] - __bfloat162float(hb));
                }
                int so = swz(n, k0);
                *(uint4*)(smem + SM_BH + so) = hv;
                *(uint4*)(smem + SM_BL + so) = lv;
            }
        }
        __syncthreads();

        // ---- compute: 3 split terms (AhBh, AlBh, AhBl) ----
        #pragma unroll
        for (int t = 0; t < 3; t++) {
            const uint32_t Aoff = (t == 1) ? SM_AL : SM_AH;
            const uint32_t Boff = (t == 2) ? SM_BL : SM_BH;
            #pragma unroll
            for (int k16 = 0; k16 < 128; k16 += 16) {
                uint32_t a[2][4];
                #pragma unroll
                for (int mt = 0; mt < 2; mt++) {
                    int row = wm + mt * 16 + (quad & 1) * 8 + lrow;
                    int col = k16 + (quad >> 1) * 8;
                    uint32_t addr = sb + Aoff + swz(row, col);
                    LDMX4(a[mt][0], a[mt][1], a[mt][2], a[mt][3], addr);
                }
                #pragma unroll
                for (int nb = 0; nb < 4; nb++) {
                    int row = wn + nb * 16 + (quad >> 1) * 8 + lrow;
                    int col = k16 + (quad & 1) * 8;
                    uint32_t addr = sb + Boff + swz(row, col);
                    uint32_t b0, b1, b2, b3;
                    LDMX4(b0, b1, b2, b3, addr);
                    #pragma unroll
                    for (int mt = 0; mt < 2; mt++) {
                        MMA16816(acc[mt][nb * 2], a[mt], b0, b1);
                        MMA16816(acc[mt][nb * 2 + 1], a[mt], b2, b3);
                    }
                }
            }
        }
        __syncthreads();
    }

    // ---- epilogue ----
    #pragma unroll
    for (int mt = 0; mt < 2; mt++) {
        int r0 = block_row + wm + mt * 16 + (lane >> 2);
        int r1 = r0 + 8;
        #pragma unroll
        for (int nt = 0; nt < 8; nt++) {
            int cb = wn + nt * 8 + (lane & 3) * 2;
            float2 p0, p1;
            p0.x = acc[mt][nt][0]; p0.y = acc[mt][nt][1];
            p1.x = acc[mt][nt][2]; p1.y = acc[mt][nt][3];
            if (MODE != 1) {
                float bx = bias[cb], by = bias[cb + 1];
                p0.x += bx; p0.y += by;
                p1.x += bx; p1.y += by;
            }
            if (r0 < NN) {
                *(float2*)(C + (long)r0 * HH + cb) = p0;
                if (MODE == 0) *(float2*)(C2 + (long)r0 * HH + cb) = p0;
            }
            if (r1 < NN) {
                *(float2*)(C + (long)r1 * HH + cb) = p1;
                if (MODE == 0) *(float2*)(C2 + (long)r1 * HH + cb) = p1;
            }
        }
    }
}

// ---------------- edge-list helpers ----------------------------------------
__device__ __forceinline__ int edge_at(const void* buf, int e) {
    if (g_is64) return (int)((const long long*)buf)[e];
    return ((const int*)buf)[e];
}

__global__ void detect64_k(const void* srcbuf) {
    const unsigned int* p = (const unsigned int*)srcbuf;
    int any = 0;
    for (int i = 1; i < 512; i += 2) any |= (p[i] != 0u);
    g_is64 = any ? 0 : 1;
}

__global__ void zero_csr_k() {
    int i = blockIdx.x * blockDim.x + threadIdx.x;
    if (i < NN) { g_deg[i] = 0; g_cursor[i] = 0; }
}

__global__ void hist_k(const void* dstbuf) {
    for (int e = blockIdx.x * blockDim.x + threadIdx.x; e < EE;
         e += gridDim.x * blockDim.x) {
        atomicAdd(&g_deg[edge_at(dstbuf, e)], 1);
    }
}

// ---- 3-phase scan ----
__global__ void scanA_k() {
    __shared__ int wt[32];
    int tid = threadIdx.x, lane = tid & 31, wid = tid >> 5;
    int i = blockIdx.x * 1024 + tid;
    int v = (i < NN) ? g_deg[i] : 0;
    int x = v;
    #pragma unroll
    for (int d = 1; d < 32; d <<= 1) {
        int y = __shfl_up_sync(0xFFFFFFFFu, x, d);
        if (lane >= d) x += y;
    }
    if (lane == 31) wt[wid] = x;
    __syncthreads();
    if (wid == 0) {
        int t = wt[lane];
        int tx = t;
        #pragma unroll
        for (int d = 1; d < 32; d <<= 1) {
            int y = __shfl_up_sync(0xFFFFFFFFu, tx, d);
            if (lane >= d) tx += y;
        }
        wt[lane] = tx - t;
    }
    __syncthreads();
    int incl = x + wt[wid];
    if (i < NN) g_rowptr[i] = incl - v;
    if (tid == 1023) g_part[blockIdx.x] = incl;
}

__global__ void scanB_k(int nblk) {
    int s = 0;
    for (int b = 0; b < nblk; b++) { g_partoff[b] = s; s += g_part[b]; }
    g_rowptr[NN] = s;
}

__global__ void scanC_k() {
    int i = blockIdx.x * 1024 + threadIdx.x;
    if (i < NN) g_rowptr[i] += g_partoff[blockIdx.x];
}

__global__ void fill_k(const void* srcbuf, const void* dstbuf) {
    for (int e = blockIdx.x * blockDim.x + threadIdx.x; e < EE;
         e += gridDim.x * blockDim.x) {
        int d = edge_at(dstbuf, e);
        int s = edge_at(srcbuf, e);
        int pos = atomicAdd(&g_cursor[d], 1);
        g_col[g_rowptr[d] + pos] = s;
    }
}

// ---------------- gather: h = 0.9 * (A @ z) + 0.1 * x0 ----------------------
__global__ void gather_k(const float* __restrict__ z,
                         const float* __restrict__ x0,
                         float* __restrict__ h) {
    int gw = (blockIdx.x * blockDim.x + threadIdx.x) >> 5;
    if (gw >= NN) return;
    int lane = threadIdx.x & 31;
    int beg = g_rowptr[gw], end = g_rowptr[gw + 1];
    float4 acc = make_float4(0.f, 0.f, 0.f, 0.f);
    int e = beg;
    for (; e + 3 < end; e += 4) {
        int s0 = g_col[e], s1 = g_col[e + 1], s2 = g_col[e + 2], s3 = g_col[e + 3];
        float4 v0 = ((const float4*)(z + (long)s0 * HH))[lane];
        float4 v1 = ((const float4*)(z + (long)s1 * HH))[lane];
        float4 v2 = ((const float4*)(z + (long)s2 * HH))[lane];
        float4 v3 = ((const float4*)(z + (long)s3 * HH))[lane];
        acc.x += (v0.x + v1.x) + (v2.x + v3.x);
        acc.y += (v0.y + v1.y) + (v2.y + v3.y);
        acc.z += (v0.z + v1.z) + (v2.z + v3.z);
        acc.w += (v0.w + v1.w) + (v2.w + v3.w);
    }
    for (; e < end; ++e) {
        int s = g_col[e];
        float4 v = ((const float4*)(z + (long)s * HH))[lane];
        acc.x += v.x; acc.y += v.y; acc.z += v.z; acc.w += v.w;
    }
    float4 xv = ((const float4*)(x0 + (long)gw * HH))[lane];
    float4 o;
    const float A1 = 0.9f, A0 = 0.1f;
    o.x = A1 * acc.x + A0 * xv.x;
    o.y = A1 * acc.y + A0 * xv.y;
    o.z = A1 * acc.z + A0 * xv.z;
    o.w = A1 * acc.w + A0 * xv.w;
    ((float4*)(h + (long)gw * HH))[lane] = o;
}

// ---------------- BatchNorm -------------------------------------------------
__global__ void zero_bn_k() {
    int c = threadIdx.x;
    g_bnsum[c] = 0.f;
    g_bnsq[c] = 0.f;
}

__global__ void bn_stats_k(const float* __restrict__ z) {
    int c = threadIdx.x;
    float s = 0.f, q = 0.f;
    for (int r = blockIdx.x; r < NN; r += gridDim.x) {
        float v = z[(long)r * HH + c];
        s += v;
        q += v * v;
    }
    atomicAdd(&g_bnsum[c], s);
    atomicAdd(&g_bnsq[c], q);
}

__global__ void bn_apply_k(const float* __restrict__ zin,
                           const float* __restrict__ gamma,
                           const float* __restrict__ beta,
                           float* __restrict__ zout) {
    int i = blockIdx.x * blockDim.x + threadIdx.x;
    if (i >= NN * HH) return;
    int c = i & (HH - 1);
    float invN = 1.0f / (float)NN;
    float m = g_bnsum[c] * invN;
    float var = g_bnsq[c] * invN - m * m;
    float r = rsqrtf(var + 1e-5f);
    float v = (zin[i] - m) * r * gamma[c] + beta[c];
    zout[i] = v > 0.f ? v : 0.f;
}

// ---------------- host orchestration ----------------------------------------
extern "C" void kernel_launch(void* const* d_in, const int* in_sizes, int n_in,
                              void* d_out, int out_size) {
    const float* x     = (const float*)d_in[0];
    const float* W_in  = (const float*)d_in[1];
    const float* b_in  = (const float*)d_in[2];
    const float* convW = (const float*)d_in[3];
    const float* gma   = (const float*)d_in[4];
    const float* bta   = (const float*)d_in[5];
    const float* W_jk  = (const float*)d_in[6];
    const float* b_jk  = (const float*)d_in[7];
    const void*  src   = d_in[8];
    const void*  dst   = d_in[9];
    float* out = (float*)d_out;

    void *pz, *px0, *ph, *pzs;
    cudaGetSymbolAddress(&pz, g_zcur);
    cudaGetSymbolAddress(&px0, g_x0);
    cudaGetSymbolAddress(&ph, g_h);
    cudaGetSymbolAddress(&pzs, g_zs);
    float* zcur = (float*)pz;
    float* x0   = (float*)px0;
    float* h    = (float*)ph;
    float* zs0  = (float*)pzs;
    float* zs1  = zs0 + (long)NN * HH;
    float* zs2  = zs1 + (long)NN * HH;
    float* zs3  = zs2 + (long)NN * HH;

    float bl[LL];
    for (int i = 0; i < LL; i++) bl[i] = (float)log(0.5 / (double)(i + 1) + 1.0);

    cudaFuncSetAttribute(gemm_tc_k<0>, cudaFuncAttributeMaxDynamicSharedMemorySize, SM_TOTAL);
    cudaFuncSetAttribute(gemm_tc_k<1>, cudaFuncAttributeMaxDynamicSharedMemorySize, SM_TOTAL);
    cudaFuncSetAttribute(gemm_tc_k<2>, cudaFuncAttributeMaxDynamicSharedMemorySize, SM_TOTAL);

    const int GEMM_BLOCKS = (NN + 127) / 128;            // 782
    const int GATHER_BLOCKS = (NN * 32 + 255) / 256;
    const int EW_BLOCKS = (NN * HH + 255) / 256;
    const int SCAN_BLOCKS = (NN + 1023) / 1024;          // 98

    // CSR build
    zero_csr_k<<<(NN + 255) / 256, 256>>>();
    detect64_k<<<1, 1>>>(src);
    hist_k<<<1024, 256>>>(dst);
    scanA_k<<<SCAN_BLOCKS, 1024>>>();
    scanB_k<<<1, 1>>>(SCAN_BLOCKS);
    scanC_k<<<SCAN_BLOCKS, 1024>>>();
    fill_k<<<1024, 256>>>(src, dst);

    // input layer: z = x @ W_in + b_in; x0 = z
    gemm_tc_k<0><<<GEMM_BLOCKS, 256, SM_TOTAL>>>(x, 0, 0, 0, W_in, b_in,
                                                 1.0f, 0.0f, zcur, x0);

    float* zsbuf[4] = {zs0, zs1, zs2, zs3};
    for (int i = 0; i < LL; i++) {
        gather_k<<<GATHER_BLOCKS, 256>>>(zcur, x0, h);
        float* Cout = (i < 4) ? zsbuf[i] : out;
        gemm_tc_k<1><<<GEMM_BLOCKS, 256, SM_TOTAL>>>(h, 0, 0, 0,
                                                     convW + (long)i * HH * HH, 0,
                                                     bl[i], 1.0f - bl[i], Cout, 0);
        if (i < 3) {
            zero_bn_k<<<1, HH>>>();
            bn_stats_k<<<512, HH>>>(zsbuf[i]);
            bn_apply_k<<<EW_BLOCKS, 256>>>(zsbuf[i], gma + i * HH, bta + i * HH, zcur);
        } else if (i == 3) {
            gemm_tc_k<2><<<GEMM_BLOCKS, 256, SM_TOTAL>>>(zs0, zs1, zs2, zs3,
                                                         W_jk, b_jk, 1.0f, 0.0f,
                                                         zcur, 0);
        }
    }
    (void)in_sizes; (void)n_in; (void)out_size;
}